// round 1
// baseline (speedup 1.0000x reference)
#include <cuda_runtime.h>

// ---------------- problem constants ----------------
#define C_      64
#define K_      15
#define H_      32
#define SIGMA_INV (1.0f / 0.7f)
#define BN_EPS  1e-5f
#define MAXN    50176   // >= 50000, margin

// ---------------- scratch (device globals; no allocation) ----------------
__device__ float g_h[MAXN * C_];        // h = s_feats @ W1 (pre-BN)
__device__ float g_part[512 * 128];     // per-block partial [sum(64), sumsq(64)]
__device__ float g_scale[C_];           // gamma / sqrt(var+eps)
__device__ float g_shift[C_];           // beta - mu*scale

// ---------------- f32x2 packed helpers (sm_103a) ----------------
__device__ __forceinline__ unsigned long long pack2(float x, float y) {
    unsigned long long r;
    asm("mov.b64 %0, {%1, %2};" : "=l"(r) : "f"(x), "f"(y));
    return r;
}
__device__ __forceinline__ void unpack2(unsigned long long v, float& x, float& y) {
    asm("mov.b64 {%0, %1}, %2;" : "=f"(x), "=f"(y) : "l"(v));
}
__device__ __forceinline__ void fma2(unsigned long long& acc,
                                     unsigned long long a, unsigned long long b) {
    asm("fma.rn.f32x2 %0, %1, %2, %0;" : "+l"(acc) : "l"(a), "l"(b));
}

// ================= K1: h = s_feats @ W1, per-block BN partials =================
__global__ void __launch_bounds__(256) k1_feat_mm(
    const float* __restrict__ s_feats, const float* __restrict__ W1, int N)
{
    __shared__ float W1s[64 * 64];
    __shared__ float feat_s[16 * 64];
    __shared__ float red[256];

    const int tid = threadIdx.x;
    for (int i = tid; i < 4096; i += 256) W1s[i] = W1[i];

    const int c  = tid & 63;
    const int rb = tid >> 6;           // 0..3 (row group within 16-row tile)
    float sum = 0.f, sumsq = 0.f;
    const int row0 = blockIdx.x * 128;

    for (int t = 0; t < 8; t++) {
        const int r0 = row0 + t * 16;
        __syncthreads();
        for (int i = tid; i < 1024; i += 256) {
            int r = i >> 6, cc = i & 63;
            feat_s[i] = (r0 + r < N) ? s_feats[(r0 + r) * 64 + cc] : 0.f;
        }
        __syncthreads();

        float acc[4] = {0.f, 0.f, 0.f, 0.f};
        #pragma unroll 8
        for (int cp = 0; cp < 64; cp++) {
            float w = W1s[cp * 64 + c];
            #pragma unroll
            for (int rr = 0; rr < 4; rr++)
                acc[rr] = fmaf(feat_s[(rb * 4 + rr) * 64 + cp], w, acc[rr]);
        }
        #pragma unroll
        for (int rr = 0; rr < 4; rr++) {
            int m = r0 + rb * 4 + rr;
            if (m < N) {
                g_h[m * 64 + c] = acc[rr];
                sum += acc[rr];
                sumsq = fmaf(acc[rr], acc[rr], sumsq);
            }
        }
    }

    __syncthreads();
    red[tid] = sum;
    __syncthreads();
    if (tid < 64)
        g_part[blockIdx.x * 128 + tid] =
            red[tid] + red[tid + 64] + red[tid + 128] + red[tid + 192];
    __syncthreads();
    red[tid] = sumsq;
    __syncthreads();
    if (tid < 64)
        g_part[blockIdx.x * 128 + 64 + tid] =
            red[tid] + red[tid + 64] + red[tid + 128] + red[tid + 192];
}

// ================= K2: finalize BN scale/shift (deterministic) =================
__global__ void __launch_bounds__(256) k2_bn(
    const float* __restrict__ gamma, const float* __restrict__ beta,
    int N, int nb)
{
    __shared__ float red[256];
    const int tid  = threadIdx.x;
    const int c    = tid & 63;
    const int part = tid >> 6;

    float s = 0.f, q = 0.f;
    for (int b = part; b < nb; b += 4) {
        s += g_part[b * 128 + c];
        q += g_part[b * 128 + 64 + c];
    }
    red[tid] = s;
    __syncthreads();
    float sum = 0.f;
    if (tid < 64) sum = red[tid] + red[tid + 64] + red[tid + 128] + red[tid + 192];
    __syncthreads();
    red[tid] = q;
    __syncthreads();
    if (tid < 64) {
        float sq  = red[tid] + red[tid + 64] + red[tid + 128] + red[tid + 192];
        float inv = 1.f / (float)N;
        float mu  = sum * inv;
        float var = sq * inv - mu * mu;
        float sc  = gamma[tid] * rsqrtf(var + BN_EPS);
        g_scale[tid] = sc;
        g_shift[tid] = beta[tid] - mu * sc;
    }
}

// ================= K3: fused weights-GEMM + gather + aggregate =================
// One block = 32 queries, 512 threads.
// smem: a_t (64 x 34 transposed activations), w_s (32 x 15 x 64 conv weights),
//       infl/ind/nn neighbor metadata, kernel points.
#define K3_SMEM_FLOATS (2176 + 30720 + 1024 + 1024 + 48)
#define K3_SMEM_BYTES  (K3_SMEM_FLOATS * 4 + 1024)

__global__ void __launch_bounds__(512, 1) k3_main(
    const float* __restrict__ q_pts, const float* __restrict__ s_pts,
    const float* __restrict__ s_feats, const int* __restrict__ neighb_inds,
    const float* __restrict__ kernel_points,
    const float* __restrict__ W2, const float* __restrict__ b2,
    float* __restrict__ out, int N)
{
    extern __shared__ float sm[];
    float* a_t    = sm;                          // 64*34 floats (8B-aligned pairs)
    float* w_s    = sm + 2176;                   // 32*15*64
    float* infl_s = w_s + 30720;                 // 1024
    int*   ind_s  = (int*)(infl_s + 1024);       // 1024
    float* kp_s   = (float*)(ind_s + 1024);      // 48 (15*3 padded)
    unsigned char* nn_s = (unsigned char*)(kp_s + 48); // 1024 bytes

    const int tid = threadIdx.x;
    const int m0  = blockIdx.x * 32;

    if (tid < 45) kp_s[tid] = kernel_points[tid];

    // ---- phase 1: a = leakyrelu(BN(h)) into transposed smem a_t[c][m] ----
    for (int i = tid; i < 2048; i += 512) {
        int m = i >> 6, c = i & 63;
        int gm = m0 + m;
        float v = 0.f;
        if (gm < N) {
            v = fmaf(g_h[gm * 64 + c], g_scale[c], g_shift[c]);
            v = (v > 0.f) ? v : 0.1f * v;
        }
        a_t[c * 34 + m] = v;
    }

    // ---- phase 2: neighbor prep (rel pos, 1-NN kernel point, influence) ----
    for (int i = tid; i < 1024; i += 512) {
        int m = i >> 5, h = i & 31;
        int gm = m0 + m;
        int ind = 0, kb = 0;
        float infl = 0.f;
        if (gm < N) {
            int id = neighb_inds[gm * 32 + h];
            if (id >= 0 && id < N) {
                ind = id;
                float qx = q_pts[gm * 3 + 0];
                float qy = q_pts[gm * 3 + 1];
                float qz = q_pts[gm * 3 + 2];
                float nx = s_pts[id * 3 + 0] - qx;
                float ny = s_pts[id * 3 + 1] - qy;
                float nz = s_pts[id * 3 + 2] - qz;
                float best = 1e30f;
                #pragma unroll
                for (int k = 0; k < 15; k++) {
                    float dx = nx - kp_s[k * 3 + 0];
                    float dy = ny - kp_s[k * 3 + 1];
                    float dz = nz - kp_s[k * 3 + 2];
                    float d = fmaf(dx, dx, fmaf(dy, dy, dz * dz));
                    if (d < best) { best = d; kb = k; }  // first-min tiebreak
                }
                infl = fmaxf(0.f, 1.f - sqrtf(best) * SIGMA_INV);
            }
        }
        ind_s[i] = ind;
        infl_s[i] = infl;
        nn_s[i] = (unsigned char)kb;
    }
    __syncthreads();

    // ---- phase 3: w[m][k][c] = a[m] @ W2[:, k*64+c] + b2  (f32x2 packed) ----
    // Thread owns columns j0, j0+1; accumulators packed over (m, m+1) pairs.
    if (tid < 480) {
        const int j0 = tid << 1;
        unsigned long long accA[16], accB[16];
        {
            float bx = __ldg(b2 + j0), by = __ldg(b2 + j0 + 1);
            unsigned long long pbx = pack2(bx, bx), pby = pack2(by, by);
            #pragma unroll
            for (int p = 0; p < 16; p++) { accA[p] = pbx; accB[p] = pby; }
        }
        #pragma unroll 4
        for (int cp = 0; cp < 64; cp++) {
            float2 wv = *reinterpret_cast<const float2*>(W2 + cp * 960 + j0);
            unsigned long long wx = pack2(wv.x, wv.x);
            unsigned long long wy = pack2(wv.y, wv.y);
            const unsigned long long* ar =
                reinterpret_cast<const unsigned long long*>(a_t + cp * 34);
            #pragma unroll
            for (int p = 0; p < 16; p++) {
                unsigned long long a2 = ar[p];   // (a[2p], a[2p+1]) broadcast LDS.64
                fma2(accA[p], a2, wx);
                fma2(accB[p], a2, wy);
            }
        }
        const int kk = j0 >> 6, c0 = j0 & 63;
        #pragma unroll
        for (int p = 0; p < 16; p++) {
            float x0, x1, y0, y1;
            unpack2(accA[p], x0, x1);
            unpack2(accB[p], y0, y1);
            int b0 = ((2 * p) * 15 + kk) << 6;
            int b1 = ((2 * p + 1) * 15 + kk) << 6;
            w_s[b0 + c0]     = x0;  w_s[b1 + c0]     = x1;
            w_s[b0 + c0 + 1] = y0;  w_s[b1 + c0 + 1] = y1;
        }
    }
    __syncthreads();

    // ---- phase 4: gather + weighted aggregation; warp owns 2 queries ----
    {
        const int wid = tid >> 5, lane = tid & 31;
        #pragma unroll
        for (int mi = 0; mi < 2; mi++) {
            int mm = wid * 2 + mi;
            int gm = m0 + mm;
            if (gm >= N) continue;
            float o0 = 0.f, o1 = 0.f;
            const int base = mm << 5;
            #pragma unroll 4
            for (int h = 0; h < 32; h++) {
                float fl = infl_s[base + h];
                int   id = ind_s[base + h];
                int   k  = nn_s[base + h];
                const float* f = s_feats + id * 64;
                float f0 = __ldg(f + lane);
                float f1 = __ldg(f + lane + 32);
                const float* wp = w_s + ((mm * 15 + k) << 6);
                float w0 = wp[lane] * fl;
                float w1 = wp[lane + 32] * fl;
                o0 = fmaf(f0, w0, o0);
                o1 = fmaf(f1, w1, o1);
            }
            out[gm * 64 + lane]      = o0;
            out[gm * 64 + lane + 32] = o1;
        }
    }
}

// ================= launch =================
extern "C" void kernel_launch(void* const* d_in, const int* in_sizes, int n_in,
                              void* d_out, int out_size)
{
    const float* q_pts   = (const float*)d_in[0];
    const float* s_pts   = (const float*)d_in[1];
    const float* s_feats = (const float*)d_in[2];
    const int*   neighb  = (const int*)d_in[3];
    const float* kp      = (const float*)d_in[4];
    const float* W1      = (const float*)d_in[5];
    const float* gamma   = (const float*)d_in[6];
    const float* beta    = (const float*)d_in[7];
    const float* W2      = (const float*)d_in[8];
    const float* b2      = (const float*)d_in[9];
    float* out = (float*)d_out;

    const int N = in_sizes[0] / 3;           // 50000
    const int nb1 = (N + 127) / 128;         // <= 392, fits g_part

    k1_feat_mm<<<nb1, 256>>>(s_feats, W1, N);
    k2_bn<<<1, 256>>>(gamma, beta, N, nb1);

    cudaFuncSetAttribute(k3_main, cudaFuncAttributeMaxDynamicSharedMemorySize,
                         K3_SMEM_BYTES);
    const int nb3 = (N + 31) / 32;
    k3_main<<<nb3, 512, K3_SMEM_BYTES>>>(q_pts, s_pts, s_feats, neighb, kp,
                                         W2, b2, out, N);
}